// round 10
// baseline (speedup 1.0000x reference)
#include <cuda_runtime.h>
#include <math_constants.h>

// ProgressReward — round 9: polyline-major, every phase chain cut to <=2 RTs.
//
// Block i owns static polyline chunk [c0,c1). Phase 1 (one global sync):
//   producer (warp 15): cycle-0 loads poly_batch[ends] AND agent_ptr window
//     around the EXPECTED batch c0*B/P (+-2); on arrival picks real span
//     [sb0,sb1]; window hit -> query loads issue immediately (2 chained RTs
//     total), miss -> fallback load (3 RTs, rare).
//   stage (warps 0-14, <=480 cands): cycle-0 loads candidates AND the int32
//     mask into smem; bar.sync(1,480); mask lookup via LDS; writes s4
//     (c,s,a|+INF,bv), batch boundaries s_bnd, and g_cs[p]=(c,s,a) for
//     phase 2.
// Eval: 8 groups x 64 queries; per-(batch,query) block winner reduced in
// smem (ascending groups), ONE atomicMax(g_win, ~packed) per block;
// packed=(dist_bits<<32)|idx => unsigned min == jnp.argmin first-min,
// order-independent. Grid spin barrier (single wave). Phase 2: block b<B
// reads 64 winners + g_cs (L2-hot, 2 RTs), reduces, writes out[b], resets
// its g_win words. Zero-init + complement + resets => graph-replay safe.

#define NUM_HIST 4
#define INTERVAL 5
#define IP_ROWS  36
#define L_ROWS   180
#define TPB      512
#define STG      480        // stage threads (warps 0-14)
#define SUBCH    480        // max candidates per sub-chunk (1 per stage thread)
#define QS       8
#define B_MAX    256
#define MASK_SM  2048
#define P_CS     24576

__device__ float4 g_cs[P_CS];                      // (c,s,a,-) per polyline
__device__ unsigned long long g_win[B_MAX * 64];   // zero-init; self-resetting
__device__ int g_sync1, g_sync2;                   // zero-init; self-resetting

__global__ void __launch_bounds__(TPB)
progress_reward_kernel(
    const int*   __restrict__ poly_batch,
    const float* __restrict__ poly_pos,
    const float* __restrict__ poly_heading,
    const int*   __restrict__ edge_index,
    const int*   __restrict__ on_route_mask,
    const int*   __restrict__ agent_ptr,
    const float* __restrict__ infer_pos,
    const int*   __restrict__ agent_batch,         // unused (CSR invariant)
    const float* __restrict__ agent_pos,
    float*       __restrict__ out,
    int P, int NG, int B)
{
    __shared__ float4 s4[SUBCH];
    __shared__ int    s_mask[MASK_SM];
    __shared__ int    s_bnd[B_MAX + 2];
    __shared__ float4 s_q[QS][64];
    __shared__ int    s_b0, s_b1;
    __shared__ int    s_aidx[QS];
    __shared__ unsigned long long red64[8][64];
    __shared__ float  s_sum[2];

    const int grid = gridDim.x;
    const int bi   = blockIdx.x;
    const int tid  = threadIdx.x;
    const int lane = tid & 31;
    const int warp = tid >> 5;
    const int g    = tid >> 6;
    const int sub  = tid & 63;
    const int role = sub >> 5;
    const int t    = sub & 31;

    const int chunk = (P + grid - 1) / grid;
    const int c0 = bi * chunk;
    const int c1 = min(c0 + chunk, P);
    const bool useSM = (NG <= MASK_SM);

    // ---- phase-2 query prefetch (independent, cycle 0) ----
    float2 p2c = make_float2(0.f, 0.f), p2p = make_float2(0.f, 0.f);
    if (bi < B && tid < 64) {
        const int a2 = agent_ptr[bi];
        if (role == 0) {
            const float2* ip = (const float2*)(infer_pos + (size_t)a2 * (IP_ROWS * 2));
            p2c = ip[NUM_HIST + t];
            p2p = ip[NUM_HIST - 1 + t];
        } else {
            const float2* ap = (const float2*)(agent_pos + (size_t)a2 * (L_ROWS * 2));
            p2c = ap[(4 + t) * INTERVAL];
            p2p = ap[(3 + t) * INTERVAL];
        }
    }

    const float2* pp2 = (const float2*)poly_pos;

    // ================= phase 1 =================
    for (int base = c0; base < c1; base += SUBCH) {
        const int cnt = min(SUBCH, c1 - base);

        if (warp == 15) {
            // ---- producer: window-prefetch + span + query staging ----
            int w0 = (int)(((long long)c0 * B) / P) - 2;      // expected batch
            if (w0 > B - 8) w0 = B - 8;
            if (w0 < 0) w0 = 0;
            int apw = 0;
            if (lane < 8 && (w0 + lane) <= B) apw = agent_ptr[w0 + lane];
            int e = 0;
            if (lane == 0) e = poly_batch[base];
            if (lane == 1) e = poly_batch[base + cnt - 1];
            const int sb0 = __shfl_sync(0xFFFFFFFFu, e, 0);
            const int sb1 = __shfl_sync(0xFFFFFFFFu, e, 1);
            if (lane == 0) { s_b0 = sb0; s_b1 = sb1; }
            if (lane == 2) s_bnd[sb1 + 1] = cnt;
            const int nq = min(sb1 - sb0 + 1, QS);
            int ax = 0;
            if ((sb0 >= w0) && (sb0 + nq - 1 <= w0 + 7)) {
                const int src = sb0 - w0 + lane;               // <32 for lane<nq
                ax = __shfl_sync(0xFFFFFFFFu, apw, src & 31);
            } else if (lane < nq) {
                ax = agent_ptr[sb0 + lane];                    // rare fallback
            }
            for (int k = 0; k < nq; k++) {
                const int a = __shfl_sync(0xFFFFFFFFu, ax, k);
                const float2* ip = (const float2*)(infer_pos + (size_t)a * (IP_ROWS * 2));
                float2 qc2 = ip[NUM_HIST + lane];
                float2 qp2 = ip[NUM_HIST - 1 + lane];
                s_q[k][lane] = make_float4(qc2.x, qc2.y, qp2.x, qp2.y);
                const float2* ap = (const float2*)(agent_pos + (size_t)a * (L_ROWS * 2));
                qc2 = ap[(4 + lane) * INTERVAL];
                qp2 = ap[(3 + lane) * INTERVAL];
                s_q[k][32 + lane] = make_float4(qc2.x, qc2.y, qp2.x, qp2.y);
            }
        } else {
            // ---- stage: candidate + mask loads all issued up front ----
            int   v = 0, vp = 0, poly = 0;
            float ch = 0.f, sh = 0.f, a = 0.f, bv = 0.f;
            const bool have = (tid < cnt);
            if (have) {
                const int p = base + tid;
                v    = poly_batch[p];
                vp   = (tid > 0) ? poly_batch[p - 1] : v;
                poly = edge_index[P + p];
                const float2 pos = pp2[p];
                const float h = poly_heading[p];
                ch = cosf(h);
                sh = sinf(h);
                a  = fmaf(ch, pos.x, sh * pos.y);
                bv = fmaf(ch, pos.y, -sh * pos.x);
            }
            if (useSM)
                for (int i = tid; i < NG; i += STG) s_mask[i] = on_route_mask[i];
            asm volatile("bar.sync 1, %0;" :: "r"(STG) : "memory");
            if (have) {
                const int p  = base + tid;
                const int on = useSM ? s_mask[poly] : on_route_mask[poly];
                float4 w;
                w.x = ch; w.y = sh;
                w.z = on ? a : CUDART_INF_F;
                w.w = bv;
                s4[tid] = w;
                if (p < P_CS) g_cs[p] = make_float4(ch, sh, a, 0.f);
                if (tid == 0) s_bnd[v] = 0;
                else
                    for (int b2 = vp + 1; b2 <= v; b2++) s_bnd[b2] = tid;
            }
        }
        __syncthreads();

        const int sb0 = s_b0;
        const int sb1 = s_b1;

        for (int bq = sb0; bq <= sb1; bq += QS) {
            const int nqw = min(QS, sb1 - bq + 1);

            if (bq != sb0) {
                // rare: span wider than QS batches -> restage queries
                __syncthreads();
                if (tid < nqw) s_aidx[tid] = agent_ptr[bq + tid];
                __syncthreads();
                if (tid < nqw * 64) {
                    const int k  = tid >> 6;
                    const int qs = tid & 63;
                    const int qr = qs >> 5, qt = qs & 31;
                    const int a  = s_aidx[k];
                    float2 qc2, qp2;
                    if (qr == 0) {
                        const float2* ip = (const float2*)(infer_pos + (size_t)a * (IP_ROWS * 2));
                        qc2 = ip[NUM_HIST + qt];
                        qp2 = ip[NUM_HIST - 1 + qt];
                    } else {
                        const float2* ap = (const float2*)(agent_pos + (size_t)a * (L_ROWS * 2));
                        qc2 = ap[(4 + qt) * INTERVAL];
                        qp2 = ap[(3 + qt) * INTERVAL];
                    }
                    s_q[k][qs] = make_float4(qc2.x, qc2.y, qp2.x, qp2.y);
                }
                __syncthreads();
            }

            for (int k = 0; k < nqw; k++) {
                const int bb = bq + k;
                const int r0 = s_bnd[bb];
                const int r1 = s_bnd[bb + 1];
                const int m  = r1 - r0;
                if (m <= 0) continue;

                const float4 q = s_q[k][sub];
                float best = CUDART_INF_F;
                int   bix  = 0;
                const int slice = (m + 7) >> 3;
                const int i0 = r0 + g * slice;
                const int i1 = min(i0 + slice, r1);
                #pragma unroll 4
                for (int i = i0; i < i1; i++) {
                    const float4 v = s4[i];
                    const float x = fmaf(v.x, q.x, fmaf(v.y, q.y, -v.z));
                    const float y = fmaf(v.x, q.y, -fmaf(v.y, q.x, v.w));
                    float d = fmaf(fabsf(y), 10.0f, fabsf(x));
                    if (x > 0.0f) d += 1000.0f;
                    if (d < best) { best = d; bix = base + i; }
                }
                red64[g][sub] = (best < CUDART_INF_F)
                    ? (((unsigned long long)__float_as_uint(best) << 32) | (unsigned)bix)
                    : ~0ULL;
                __syncthreads();

                if (tid < 64) {
                    unsigned long long mn = red64[0][tid];
                    #pragma unroll
                    for (int gg = 1; gg < 8; gg++) {
                        const unsigned long long w = red64[gg][tid];
                        if (w < mn) mn = w;
                    }
                    if (mn != ~0ULL)
                        atomicMax(&g_win[bb * 64 + tid], ~mn);
                }
                __syncthreads();
            }
        }
        __syncthreads();
    }

    // ================= grid barrier =================
    __threadfence();
    if (tid == 0) {
        atomicAdd(&g_sync1, 1);
        while (*(volatile int*)&g_sync1 < grid) { }
    }
    __syncthreads();
    __threadfence();

    // ================= phase 2 =================
    if (bi < B && tid < 64) {
        const unsigned long long w = ~g_win[bi * 64 + tid];
        g_win[bi * 64 + tid] = 0;                  // reset for next replay
        float prog = 0.0f;
        const unsigned dbits = (unsigned)(w >> 32);
        if (dbits < 0x7F800000u) {
            const int idx = (int)(unsigned)w;
            float ch, sh, a;
            if (idx < P_CS) {
                const float4 cs = g_cs[idx];
                ch = cs.x; sh = cs.y; a = cs.z;
            } else {
                const float2 pos = pp2[idx];
                const float h = poly_heading[idx];
                ch = cosf(h); sh = sinf(h);
                a = fmaf(ch, pos.x, sh * pos.y);
            }
            const float x  = fmaf(ch, p2c.x, fmaf(sh, p2c.y, -a));
            const float xp = fmaf(ch, p2p.x, fmaf(sh, p2p.y, -a));
            prog = x - xp;
        }
        #pragma unroll
        for (int o = 16; o > 0; o >>= 1)
            prog += __shfl_down_sync(0xFFFFFFFFu, prog, o);
        if (t == 0) s_sum[role] = prog;
    }
    __syncthreads();
    if (bi < B && tid == 0)
        out[bi] = fminf(fmaxf(s_sum[0], 2.0f) / fmaxf(s_sum[1], 2.0f), 1.0f);

    if (tid == 0) {
        if (atomicAdd(&g_sync2, 1) == grid - 1) {
            g_sync1 = 0;
            g_sync2 = 0;
        }
    }
}

extern "C" void kernel_launch(void* const* d_in, const int* in_sizes, int n_in,
                              void* d_out, int out_size)
{
    const int*   poly_batch    = (const int*)  d_in[0];
    const float* poly_pos      = (const float*)d_in[1];
    const float* poly_heading  = (const float*)d_in[2];
    const int*   edge_index    = (const int*)  d_in[3];
    const int*   on_route_mask = (const int*)  d_in[4];
    const int*   agent_ptr     = (const int*)  d_in[5];
    const float* infer_pos     = (const float*)d_in[6];
    const int*   agent_batch   = (const int*)  d_in[7];
    const float* agent_pos     = (const float*)d_in[8];
    float*       out           = (float*)      d_out;

    const int P  = in_sizes[0];
    const int NG = in_sizes[4];
    int B        = in_sizes[5] - 1;
    if (B > B_MAX) B = B_MAX;

    int grid = 128;                            // single wave for spin barrier
    if (B > grid) grid = (B <= 148) ? B : 148;

    progress_reward_kernel<<<grid, TPB>>>(
        poly_batch, poly_pos, poly_heading, edge_index, on_route_mask,
        agent_ptr, infer_pos, agent_batch, agent_pos, out, P, NG, B);
}